// round 4
// baseline (speedup 1.0000x reference)
#include <cuda_runtime.h>
#include <cuda_bf16.h>
#include <cstdint>

// Shapes (fixed)
#define Bb  4
#define Qq  100
#define Cc  81
#define Mm  50
#define HWN 65536

// Tiling
#define SPL 36            // K-splits per batch; grid = 36 x 4 = 144 CTAs (1 wave)
#define KC  64            // k-elements per stage
#define PW  56            // padded partial row width in scratch

// fp32 cp.async ring: 3 stages of (100 X-rows + 50 T-rows) x 64 fp32
#define NR       3
#define FROW     256                     // 64 floats per row
#define XF_BYTES (100 * FROW)            // 25600
#define FSTAGE   (XF_BYTES + 50 * FROW)  // 38400
#define RING     (NR * FSTAGE)           // 115200

// bf16 tiles: rows stride 144B (36 words) -> conflict-free ldmatrix
#define RS     144
#define SS_OFF (128 * RS)
#define TS_OFF (2 * 128 * RS)
#define STAGE  (2 * 128 * RS + 64 * RS)  // 46080
#define BF_OFF RING
#define SMEM_BYTES (RING + 2 * STAGE)    // 207360

// -------- device scratch (static; no allocations) --------
__device__ float g_px[(size_t)Bb * SPL * Qq * PW];
__device__ float g_ps[(size_t)Bb * SPL * Qq * PW];
__device__ float g_spp[Bb * SPL * Qq];
__device__ float g_sgp[Bb * SPL * Qq];
__device__ float g_tsp[Bb * SPL * Mm];

__device__ __forceinline__ uint32_t s2u(const void* p) {
    uint32_t a;
    asm("{ .reg .u64 t; cvta.to.shared.u64 t, %1; cvt.u32.u64 %0, t; }" : "=r"(a) : "l"(p));
    return a;
}
__device__ __forceinline__ void cpa16(uint32_t dst, const void* src) {
    asm volatile("cp.async.cg.shared.global [%0], [%1], 16;" :: "r"(dst), "l"(src));
}
__device__ __forceinline__ void ldsm4(uint32_t* r, uint32_t a) {
    asm volatile("ldmatrix.sync.aligned.m8n8.x4.shared.b16 {%0,%1,%2,%3}, [%4];"
                 : "=r"(r[0]), "=r"(r[1]), "=r"(r[2]), "=r"(r[3]) : "r"(a));
}
__device__ __forceinline__ void mma16816(float* c, const uint32_t* a, uint32_t b0, uint32_t b1) {
    asm volatile("mma.sync.aligned.m16n8k16.row.col.f32.bf16.bf16.f32 "
                 "{%0,%1,%2,%3}, {%4,%5,%6,%7}, {%8,%9}, {%0,%1,%2,%3};"
                 : "+f"(c[0]), "+f"(c[1]), "+f"(c[2]), "+f"(c[3])
                 : "r"(a[0]), "r"(a[1]), "r"(a[2]), "r"(a[3]), "r"(b0), "r"(b1));
}

// ================= fused convert + dual bf16 mma.sync GEMM =================
__global__ __launch_bounds__(256, 1)
void cost_main(const float* __restrict__ X, const float* __restrict__ T) {
    extern __shared__ char smem[];
    const uint32_t sm0 = s2u(smem);

    const int tid = threadIdx.x;
    const int l   = tid & 31;
    const int wid = tid >> 5;
    const int wr  = wid >> 1;          // warp row 0..3  (32 q-rows each)
    const int wc  = wid & 1;           // warp col 0..1  (32 m-cols each)
    const int rb  = tid >> 4;          // 0..15 load row
    const int cg  = tid & 15;          // 0..15 column group (4 floats)

    const int split = blockIdx.x;
    const int b     = blockIdx.y;
    const int nst   = (split < 16) ? 29 : 28;
    const int k0    = (split * 28 + min(split, 16)) * KC;

    const float* Xb = X + (size_t)b * Qq * HWN;
    const float* Tb = T + (size_t)b * Mm * HWN;

    // ldmatrix per-lane base addresses (within bf16 region, buf 0)
    const uint32_t sA0 = sm0 + BF_OFF + (uint32_t)(wr * 32 + (l & 15)) * RS + ((l >> 4) & 1) * 16;
    const uint32_t sA1 = sA0 + 16 * RS;
    const uint32_t sS0 = sA0 + SS_OFF;
    const uint32_t sS1 = sA1 + SS_OFF;
    const uint32_t sB0 = sm0 + BF_OFF + TS_OFF +
        (uint32_t)(wc * 32 + (l & 7) + ((l >> 4) & 1) * 8) * RS + ((l >> 3) & 1) * 16;
    const uint32_t sB1 = sB0 + 16 * RS;

    // fp32 ring per-thread addresses
    const uint32_t fX = sm0 + (uint32_t)rb * FROW + (uint32_t)cg * 16;
    const uint32_t fT = fX + XF_BYTES;

    float accx[2][4][4], accs[2][4][4];
#pragma unroll
    for (int i = 0; i < 2; i++)
#pragma unroll
        for (int j = 0; j < 4; j++)
#pragma unroll
            for (int k = 0; k < 4; k++) { accx[i][j][k] = 0.f; accs[i][j][k] = 0.f; }

    float sp_acc[7] = {0,0,0,0,0,0,0};
    float sg_acc[7] = {0,0,0,0,0,0,0};
    float ts_acc[4] = {0,0,0,0};

    // cp.async issue for one stage (each thread copies what it will convert)
    auto issue_cp = [&](int s) {
        const uint32_t slot = (uint32_t)(s % NR) * FSTAGE;
        const int kg = k0 + s * KC + 4 * cg;
#pragma unroll
        for (int i = 0; i < 7; i++) {
            const int r = rb + 16 * i;
            if (r < Qq) cpa16(fX + slot + (uint32_t)(16 * i) * FROW,
                              Xb + (size_t)r * HWN + kg);
        }
#pragma unroll
        for (int i = 0; i < 4; i++) {
            const int r = rb + 16 * i;
            if (r < Mm) cpa16(fT + slot + (uint32_t)(16 * i) * FROW,
                              Tb + (size_t)r * HWN + kg);
        }
    };

    // prologue: stages 0 and 1 in flight
    issue_cp(0); asm volatile("cp.async.commit_group;");
    issue_cp(1); asm volatile("cp.async.commit_group;");

    for (int s = 0; s < nst; s++) {
        const int buf = s & 1;
        char* const bufp = smem + BF_OFF + buf * STAGE;
        const uint32_t slot = (uint32_t)(s % NR) * FSTAGE;

        // own data for stage s is in the oldest pending group
        asm volatile("cp.async.wait_group 1;" ::: "memory");

        // keep the pipe full (empty commit keeps group accounting uniform)
        if (s + 2 < nst) issue_cp(s + 2);
        asm volatile("cp.async.commit_group;");

        // ---- convert fp32 smem -> bf16 smem ----
#pragma unroll
        for (int i = 0; i < 7; i++) {
            const int r = rb + 16 * i;
            if (r < Qq) {
                const float4 v = *(const float4*)(smem + (fX - sm0) + slot + 16 * i * FROW);
                const float xs[4] = {v.x, v.y, v.z, v.w};
                float sg[4];
#pragma unroll
                for (int j = 0; j < 4; j++) {
                    const float xx = xs[j];
                    float th;
                    asm("tanh.approx.f32 %0, %1;" : "=f"(th) : "f"(0.5f * xx));
                    const float sv = fmaf(0.5f, th, 0.5f);
                    sg[j] = sv;
                    sg_acc[i] += sv;
                    sp_acc[i] += fmaxf(xx, 0.f) - __logf(fmaf(0.5f, fabsf(th), 0.5f));
                }
                __nv_bfloat162 hx0 = __float22bfloat162_rn(make_float2(xs[0], xs[1]));
                __nv_bfloat162 hx1 = __float22bfloat162_rn(make_float2(xs[2], xs[3]));
                __nv_bfloat162 hs0 = __float22bfloat162_rn(make_float2(sg[0], sg[1]));
                __nv_bfloat162 hs1 = __float22bfloat162_rn(make_float2(sg[2], sg[3]));
                char* const p = bufp + r * RS + cg * 8;
                *reinterpret_cast<uint2*>(p) =
                    make_uint2(*reinterpret_cast<uint32_t*>(&hx0), *reinterpret_cast<uint32_t*>(&hx1));
                *reinterpret_cast<uint2*>(p + SS_OFF) =
                    make_uint2(*reinterpret_cast<uint32_t*>(&hs0), *reinterpret_cast<uint32_t*>(&hs1));
            }
        }
#pragma unroll
        for (int i = 0; i < 4; i++) {
            const int r = rb + 16 * i;
            if (r < Mm) {
                const float4 w = *(const float4*)(smem + (fT - sm0) + slot + 16 * i * FROW);
                ts_acc[i] += w.x + w.y + w.z + w.w;
                __nv_bfloat162 h0 = __float22bfloat162_rn(make_float2(w.x, w.y));
                __nv_bfloat162 h1 = __float22bfloat162_rn(make_float2(w.z, w.w));
                *reinterpret_cast<uint2*>(bufp + TS_OFF + r * RS + cg * 8) =
                    make_uint2(*reinterpret_cast<uint32_t*>(&h0), *reinterpret_cast<uint32_t*>(&h1));
            }
        }

        __syncthreads();

        // ---- dual mma over KC=64 (4 k16-steps) ----
        const uint32_t boff = (uint32_t)buf * STAGE;
#pragma unroll
        for (int st = 0; st < 4; st++) {
            const uint32_t so = boff + st * 32;
            uint32_t ax0[4], ax1[4], as0[4], as1[4], bb0[4], bb1[4];
            ldsm4(ax0, sA0 + so); ldsm4(ax1, sA1 + so);
            ldsm4(as0, sS0 + so); ldsm4(as1, sS1 + so);
            ldsm4(bb0, sB0 + so); ldsm4(bb1, sB1 + so);
            const uint32_t bfr[4][2] = {{bb0[0], bb0[1]}, {bb0[2], bb0[3]},
                                        {bb1[0], bb1[1]}, {bb1[2], bb1[3]}};
#pragma unroll
            for (int fc = 0; fc < 4; fc++) {
                mma16816(accx[0][fc], ax0, bfr[fc][0], bfr[fc][1]);
                mma16816(accx[1][fc], ax1, bfr[fc][0], bfr[fc][1]);
                mma16816(accs[0][fc], as0, bfr[fc][0], bfr[fc][1]);
                mma16816(accs[1][fc], as1, bfr[fc][0], bfr[fc][1]);
            }
        }
        // 2-buffer, 1-sync safety: convert(s+2) runs after sync(s+1), which
        // is after every warp's mma(s) on the same buffer.
    }

    // ---- row-sum reductions (16 lanes share a row) -> scratch ----
#pragma unroll
    for (int i = 0; i < 7; i++) {
        float v1 = sp_acc[i], v2 = sg_acc[i];
#pragma unroll
        for (int off = 8; off; off >>= 1) {
            v1 += __shfl_down_sync(0xffffffffu, v1, off, 16);
            v2 += __shfl_down_sync(0xffffffffu, v2, off, 16);
        }
        const int r = rb + 16 * i;
        if (cg == 0 && r < Qq) {
            g_spp[(b * SPL + split) * Qq + r] = v1;
            g_sgp[(b * SPL + split) * Qq + r] = v2;
        }
    }
#pragma unroll
    for (int i = 0; i < 4; i++) {
        float v = ts_acc[i];
#pragma unroll
        for (int off = 8; off; off >>= 1) v += __shfl_down_sync(0xffffffffu, v, off, 16);
        const int r = rb + 16 * i;
        if (cg == 0 && r < Mm) g_tsp[(b * SPL + split) * Mm + r] = v;
    }

    // ---- write mma partials to scratch ----
    {
        const size_t base = (size_t)(b * SPL + split) * Qq;
        const int ql = l >> 2;
        const int mo = 2 * (l & 3);
#pragma unroll
        for (int fr = 0; fr < 2; fr++)
#pragma unroll
            for (int fc = 0; fc < 4; fc++) {
                const int m = wc * 32 + fc * 8 + mo;
                if (m < Mm) {
                    const int q = wr * 32 + fr * 16 + ql;
                    if (q < Qq) {
                        *(float2*)&g_px[(base + q) * PW + m] =
                            make_float2(accx[fr][fc][0], accx[fr][fc][1]);
                        *(float2*)&g_ps[(base + q) * PW + m] =
                            make_float2(accs[fr][fc][0], accs[fr][fc][1]);
                    }
                    if (q + 8 < Qq) {
                        *(float2*)&g_px[(base + q + 8) * PW + m] =
                            make_float2(accx[fr][fc][2], accx[fr][fc][3]);
                        *(float2*)&g_ps[(base + q + 8) * PW + m] =
                            make_float2(accs[fr][fc][2], accs[fr][fc][3]);
                    }
                }
            }
    }
}

// ================= finalize: reduce splits + softmax + assemble =================
__global__ __launch_bounds__(512)
void finalize_k(const float* __restrict__ logits,
                const unsigned int* __restrict__ ids,
                float* __restrict__ out) {
    const int bq = blockIdx.x;           // 0..B*Q-1
    const int b  = bq / Qq;
    const int q  = bq % Qq;
    const int tid = threadIdx.x;
    __shared__ float se[Cc];
    __shared__ float sinv, ssp, ssg;
    __shared__ float red_x[8][PW], red_s[8][PW], red_t[8][PW];
    __shared__ int s64;

    if (tid == 0) s64 = 1;
    if (tid < Cc) se[tid] = logits[bq * Cc + tid];
    __syncthreads();
    if (tid < 100 && ids[2 * tid + 1] != 0u) s64 = 0;  // int64 high words all zero
    if (tid == 0) {
        float mx = se[0];
        for (int c = 1; c < Cc; c++) mx = fmaxf(mx, se[c]);
        float sm = 0.f;
        for (int c = 0; c < Cc; c++) { float e = __expf(se[c] - mx); se[c] = e; sm += e; }
        sinv = __fdividef(1.0f, sm);
    }
    // per-q softplus/sigmoid totals (warp 1)
    if (tid >= 32 && tid < 64) {
        const int ll = tid - 32;
        float vsp = 0.f, vsg = 0.f;
        for (int s = ll; s < SPL; s += 32) {
            vsp += g_spp[(b * SPL + s) * Qq + q];
            vsg += g_sgp[(b * SPL + s) * Qq + q];
        }
#pragma unroll
        for (int off = 16; off; off >>= 1) {
            vsp += __shfl_down_sync(0xffffffffu, vsp, off);
            vsg += __shfl_down_sync(0xffffffffu, vsg, off);
        }
        if (ll == 0) { ssp = vsp; ssg = vsg; }
    }
    // per-(q,m) partial sums over 36 splits, 8-way split-parallel
    {
        const int sc = tid >> 6, r = tid & 63;
        if (r < Mm) {
            float ax = 0.f, as_ = 0.f, at = 0.f;
            for (int s = sc; s < SPL; s += 8) {
                const size_t base = ((size_t)(b * SPL + s) * Qq + q) * PW + r;
                ax  += g_px[base];
                as_ += g_ps[base];
                at  += g_tsp[(b * SPL + s) * Mm + r];
            }
            red_x[sc][r] = ax; red_s[sc][r] = as_; red_t[sc][r] = at;
        }
    }
    __syncthreads();
    if (tid < Mm) {
        const int m = tid;
        float ax = 0.f, as_ = 0.f, at = 0.f;
#pragma unroll
        for (int k = 0; k < 8; k++) {
            ax += red_x[k][m]; as_ += red_s[k][m]; at += red_t[k][m];
        }
        const unsigned id = s64 ? ids[2 * (b * Mm + m)] : ids[b * Mm + m];
        const float prob  = se[id] * sinv;
        const float spm   = ssp * (1.0f / (float)HWN);
        const float denom = ssg + at + 1e-6f;
        out[bq * Mm + m] = -prob + (spm - ax * (1.0f / (float)HWN)) + 1.0f - 2.0f * as_ / denom;
    }
}

extern "C" void kernel_launch(void* const* d_in, const int* in_sizes, int n_in,
                              void* d_out, int out_size) {
    const float*        logits = (const float*)d_in[0];        // [B,Q,C]
    const float*        pmask  = (const float*)d_in[1];        // [B,Q,H,W]
    const unsigned int* ids    = (const unsigned int*)d_in[2]; // [B,M] int32 or int64
    const float*        tmask  = (const float*)d_in[3];        // [B,M,H,W]
    float*              out    = (float*)d_out;                // [B,Q,M]

    cudaFuncSetAttribute(cost_main, cudaFuncAttributeMaxDynamicSharedMemorySize, SMEM_BYTES);
    dim3 grid(SPL, Bb);
    cost_main<<<grid, 256, SMEM_BYTES>>>(pmask, tmask);
    finalize_k<<<Bb * Qq, 512>>>(logits, ids, out);
}

// round 6
// speedup vs baseline: 1.0011x; 1.0011x over previous
#include <cuda_runtime.h>
#include <cuda_bf16.h>
#include <cstdint>

// Shapes (fixed)
#define Bb  4
#define Qq  100
#define Cc  81
#define Mm  50
#define HWN 65536

// Tiling
#define SPL 36            // K-splits per batch; grid = 36 x 4 = 144 CTAs (1 wave)
#define KC  64            // k-elements per stage
#define PW2 52            // padded m-width in scratch (50 -> 52)

// fp32 cp.async ring: 3 stages of (100 X-rows + 50 T-rows) x 64 fp32
#define NR       3
#define FROW     256                     // 64 floats per row
#define XF_BYTES (100 * FROW)            // 25600
#define FSTAGE   (XF_BYTES + 50 * FROW)  // 38400
#define RING     (NR * FSTAGE)           // 115200

// bf16 tiles: rows stride 144B -> conflict-free ldmatrix
#define RS     144
#define SS_OFF (128 * RS)
#define TS_OFF (2 * 128 * RS)
#define STAGE  (2 * 128 * RS + 64 * RS)  // 46080
#define BF_OFF RING
#define SMEM_BYTES (RING + 2 * STAGE)    // 207360

// -------- device scratch (static; no allocations) --------
// layouts transposed for coalesced finalize reads: [(b,q), split, ...]
__device__ float g_px[(size_t)Bb * Qq * SPL * PW2];  // x.t partials
__device__ float g_ps[(size_t)Bb * Qq * SPL * PW2];  // sig.t partials
__device__ float g_spp[Bb * Qq * SPL];               // softplus row partials
__device__ float g_sgp[Bb * Qq * SPL];               // tanh row partials
__device__ float g_tsp[Bb * SPL * Mm];               // t row partials

__device__ __forceinline__ uint32_t s2u(const void* p) {
    uint32_t a;
    asm("{ .reg .u64 t; cvta.to.shared.u64 t, %1; cvt.u32.u64 %0, t; }" : "=r"(a) : "l"(p));
    return a;
}
__device__ __forceinline__ void cpa16(uint32_t dst, const void* src) {
    asm volatile("cp.async.cg.shared.global [%0], [%1], 16;" :: "r"(dst), "l"(src));
}
__device__ __forceinline__ void ldsm4(uint32_t* r, uint32_t a) {
    asm volatile("ldmatrix.sync.aligned.m8n8.x4.shared.b16 {%0,%1,%2,%3}, [%4];"
                 : "=r"(r[0]), "=r"(r[1]), "=r"(r[2]), "=r"(r[3]) : "r"(a));
}
__device__ __forceinline__ void mma16816(float* c, const uint32_t* a, uint32_t b0, uint32_t b1) {
    asm volatile("mma.sync.aligned.m16n8k16.row.col.f32.bf16.bf16.f32 "
                 "{%0,%1,%2,%3}, {%4,%5,%6,%7}, {%8,%9}, {%0,%1,%2,%3};"
                 : "+f"(c[0]), "+f"(c[1]), "+f"(c[2]), "+f"(c[3])
                 : "r"(a[0]), "r"(a[1]), "r"(a[2]), "r"(a[3]), "r"(b0), "r"(b1));
}

// ================= fused convert + dual bf16 mma GEMM, overlapped =================
__global__ __launch_bounds__(256, 1)
void cost_main(const float* __restrict__ X, const float* __restrict__ T) {
    extern __shared__ char smem[];
    const uint32_t sm0 = s2u(smem);

    const int tid = threadIdx.x;
    const int l   = tid & 31;
    const int wid = tid >> 5;
    const int wr  = wid >> 1;          // warp row 0..3
    const int wc  = wid & 1;           // warp col 0..1
    const int rb  = tid >> 4;          // 0..15 load row
    const int cg  = tid & 15;          // 0..15 column group

    const int split = blockIdx.x;
    const int b     = blockIdx.y;
    const int nst   = (split < 16) ? 29 : 28;
    const int k0    = (split * 28 + min(split, 16)) * KC;

    const float* Xb = X + (size_t)b * Qq * HWN;
    const float* Tb = T + (size_t)b * Mm * HWN;

    // ldmatrix per-lane base addresses (bf16 region, buf 0)
    const uint32_t sA0 = sm0 + BF_OFF + (uint32_t)(wr * 32 + (l & 15)) * RS + ((l >> 4) & 1) * 16;
    const uint32_t sA1 = sA0 + 16 * RS;
    const uint32_t sS0 = sA0 + SS_OFF;
    const uint32_t sS1 = sA1 + SS_OFF;
    const uint32_t sB0 = sm0 + BF_OFF + TS_OFF +
        (uint32_t)(wc * 32 + (l & 7) + ((l >> 4) & 1) * 8) * RS + ((l >> 3) & 1) * 16;
    const uint32_t sB1 = sB0 + 16 * RS;

    // fp32 ring per-thread byte offsets
    const uint32_t fXo = (uint32_t)rb * FROW + (uint32_t)cg * 16;
    const uint32_t fTo = fXo + XF_BYTES;

    float accx[2][4][4], accs[2][4][4];
#pragma unroll
    for (int i = 0; i < 2; i++)
#pragma unroll
        for (int j = 0; j < 4; j++)
#pragma unroll
            for (int k = 0; k < 4; k++) { accx[i][j][k] = 0.f; accs[i][j][k] = 0.f; }

    float xa[7] = {0,0,0,0,0,0,0};   // sum x
    float ta[7] = {0,0,0,0,0,0,0};   // sum tanh(x/2)
    float la[7] = {0,0,0,0,0,0,0};   // sum lg2(sigmoid(x))
    float ts_acc[4] = {0,0,0,0};

    auto issue_cp = [&](int s) {
        const uint32_t slot = (uint32_t)(s % NR) * FSTAGE;
        const int kg = k0 + s * KC + 4 * cg;
#pragma unroll
        for (int i = 0; i < 7; i++) {
            const int r = rb + 16 * i;
            if (r < Qq) cpa16(sm0 + fXo + slot + (uint32_t)(16 * i) * FROW,
                              Xb + (size_t)r * HWN + kg);
        }
#pragma unroll
        for (int i = 0; i < 4; i++) {
            const int r = rb + 16 * i;
            if (r < Mm) cpa16(sm0 + fTo + slot + (uint32_t)(16 * i) * FROW,
                              Tb + (size_t)r * HWN + kg);
        }
    };

    // convert one X row-chunk of stage sn into bf16 buffer (sn&1)
    auto convX = [&](int sn, int i) {
        const int r = rb + 16 * i;
        if (r < Qq) {
            const uint32_t slot = (uint32_t)(sn % NR) * FSTAGE;
            const float4 v = *(const float4*)(smem + fXo + slot + 16 * i * FROW);
            char* const bufp = smem + BF_OFF + (sn & 1) * STAGE;
            const float xs[4] = {v.x, v.y, v.z, v.w};
            float sv[4];
#pragma unroll
            for (int j = 0; j < 4; j++) {
                const float xx = xs[j];
                float th;
                asm("tanh.approx.f32 %0, %1;" : "=f"(th) : "f"(0.5f * xx));
                const float s_ = fmaf(0.5f, th, 0.5f);
                sv[j] = s_;
                float lg;
                asm("lg2.approx.f32 %0, %1;" : "=f"(lg) : "f"(s_));
                xa[i] += xx; ta[i] += th; la[i] += lg;
            }
            __nv_bfloat162 hx0 = __float22bfloat162_rn(make_float2(xs[0], xs[1]));
            __nv_bfloat162 hx1 = __float22bfloat162_rn(make_float2(xs[2], xs[3]));
            __nv_bfloat162 hs0 = __float22bfloat162_rn(make_float2(sv[0], sv[1]));
            __nv_bfloat162 hs1 = __float22bfloat162_rn(make_float2(sv[2], sv[3]));
            char* const p = bufp + r * RS + cg * 8;
            *reinterpret_cast<uint2*>(p) =
                make_uint2(*reinterpret_cast<uint32_t*>(&hx0), *reinterpret_cast<uint32_t*>(&hx1));
            *reinterpret_cast<uint2*>(p + SS_OFF) =
                make_uint2(*reinterpret_cast<uint32_t*>(&hs0), *reinterpret_cast<uint32_t*>(&hs1));
        }
    };
    auto convT = [&](int sn) {
        const uint32_t slot = (uint32_t)(sn % NR) * FSTAGE;
        char* const bufp = smem + BF_OFF + (sn & 1) * STAGE + TS_OFF;
#pragma unroll
        for (int i = 0; i < 4; i++) {
            const int r = rb + 16 * i;
            if (r < Mm) {
                const float4 w = *(const float4*)(smem + fTo + slot + 16 * i * FROW);
                ts_acc[i] += w.x + w.y + w.z + w.w;
                __nv_bfloat162 h0 = __float22bfloat162_rn(make_float2(w.x, w.y));
                __nv_bfloat162 h1 = __float22bfloat162_rn(make_float2(w.z, w.w));
                *reinterpret_cast<uint2*>(bufp + r * RS + cg * 8) =
                    make_uint2(*reinterpret_cast<uint32_t*>(&h0), *reinterpret_cast<uint32_t*>(&h1));
            }
        }
    };
    // one k16-step of the dual mma on buffer offset bo
    auto kstep = [&](uint32_t bo, int st) {
        const uint32_t so = bo + st * 32;
        uint32_t ax0[4], ax1[4], as0[4], as1[4], bb0[4], bb1[4];
        ldsm4(ax0, sA0 + so); ldsm4(ax1, sA1 + so);
        ldsm4(as0, sS0 + so); ldsm4(as1, sS1 + so);
        ldsm4(bb0, sB0 + so); ldsm4(bb1, sB1 + so);
        const uint32_t bfr[4][2] = {{bb0[0], bb0[1]}, {bb0[2], bb0[3]},
                                    {bb1[0], bb1[1]}, {bb1[2], bb1[3]}};
#pragma unroll
        for (int fc = 0; fc < 4; fc++) {
            mma16816(accx[0][fc], ax0, bfr[fc][0], bfr[fc][1]);
            mma16816(accx[1][fc], ax1, bfr[fc][0], bfr[fc][1]);
            mma16816(accs[0][fc], as0, bfr[fc][0], bfr[fc][1]);
            mma16816(accs[1][fc], as1, bfr[fc][0], bfr[fc][1]);
        }
    };

    // prologue: stages 0,1 in flight; convert stage 0
    issue_cp(0); asm volatile("cp.async.commit_group;");
    issue_cp(1); asm volatile("cp.async.commit_group;");
    asm volatile("cp.async.wait_group 1;" ::: "memory");
#pragma unroll
    for (int i = 0; i < 7; i++) convX(0, i);
    convT(0);
    __syncthreads();

    for (int s = 0; s < nst; s++) {
        if (s + 2 < nst) issue_cp(s + 2);
        asm volatile("cp.async.commit_group;");
        asm volatile("cp.async.wait_group 1;" ::: "memory");  // stage s+1 fp32 ready

        const uint32_t bo = (uint32_t)(s & 1) * STAGE;
        const bool cvt = (s + 1 < nst);
        // interleave mma(s) with convert(s+1) -> tensor/MUFU/FMA pipes overlap
        if (cvt) { convX(s + 1, 0); convX(s + 1, 1); }
        kstep(bo, 0);
        if (cvt) { convX(s + 1, 2); convX(s + 1, 3); }
        kstep(bo, 1);
        if (cvt) { convX(s + 1, 4); convX(s + 1, 5); }
        kstep(bo, 2);
        if (cvt) { convX(s + 1, 6); convT(s + 1); }
        kstep(bo, 3);
        __syncthreads();
        // buffer safety: convert(s+2) (iter s+1) writes buf s&1 only after this
        // barrier, i.e. after every warp's mma(s) on that buffer.
    }

    // ---- row-stat reductions (16 lanes share a row) -> scratch ----
#pragma unroll
    for (int i = 0; i < 7; i++) {
        float v1 = xa[i], v2 = ta[i], v3 = la[i];
#pragma unroll
        for (int off = 8; off; off >>= 1) {
            v1 += __shfl_down_sync(0xffffffffu, v1, off, 16);
            v2 += __shfl_down_sync(0xffffffffu, v2, off, 16);
            v3 += __shfl_down_sync(0xffffffffu, v3, off, 16);
        }
        const int r = rb + 16 * i;
        if (cg == 0 && r < Qq) {
            // softplus partial = sum(x) - ln2 * sum(lg2(sigmoid))
            g_spp[(b * Qq + r) * SPL + split] = v1 - 0.69314718f * v3;
            g_sgp[(b * Qq + r) * SPL + split] = v2;   // sum tanh(x/2)
        }
    }
#pragma unroll
    for (int i = 0; i < 4; i++) {
        float v = ts_acc[i];
#pragma unroll
        for (int off = 8; off; off >>= 1) v += __shfl_down_sync(0xffffffffu, v, off, 16);
        const int r = rb + 16 * i;
        if (cg == 0 && r < Mm) g_tsp[(b * SPL + split) * Mm + r] = v;
    }

    // ---- write mma partials: [(b,q), split, m] ----
    {
        const int ql = l >> 2;
        const int mo = 2 * (l & 3);
#pragma unroll
        for (int fr = 0; fr < 2; fr++)
#pragma unroll
            for (int fc = 0; fc < 4; fc++) {
                const int m = wc * 32 + fc * 8 + mo;
                if (m < Mm) {
                    const int q = wr * 32 + fr * 16 + ql;
                    if (q < Qq) {
                        const size_t idx = ((size_t)(b * Qq + q) * SPL + split) * PW2 + m;
                        *(float2*)&g_px[idx] = make_float2(accx[fr][fc][0], accx[fr][fc][1]);
                        *(float2*)&g_ps[idx] = make_float2(accs[fr][fc][0], accs[fr][fc][1]);
                    }
                    if (q + 8 < Qq) {
                        const size_t idx = ((size_t)(b * Qq + q + 8) * SPL + split) * PW2 + m;
                        *(float2*)&g_px[idx] = make_float2(accx[fr][fc][2], accx[fr][fc][3]);
                        *(float2*)&g_ps[idx] = make_float2(accs[fr][fc][2], accs[fr][fc][3]);
                    }
                }
            }
    }
}

// ================= finalize: coalesced reduce + softmax + assemble =================
__global__ __launch_bounds__(512)
void finalize_k(const float* __restrict__ logits,
                const unsigned int* __restrict__ ids,
                float* __restrict__ out) {
    const int bq = blockIdx.x;           // 0..B*Q-1
    const int b  = bq / Qq;
    const int tid = threadIdx.x;
    __shared__ float se[Cc];
    __shared__ __align__(16) float sx[SPL][PW2];    // 16B aligned: float4-accessed
    __shared__ __align__(16) float ss_[SPL][PW2];
    __shared__ float spv[SPL], sgv[SPL];
    __shared__ float sinv, ssp, ssg;
    __shared__ int s64;

    if (tid == 0) s64 = 1;
    if (tid < Cc) se[tid] = logits[bq * Cc + tid];
    if (tid < 100 && ids[2 * tid + 1] != 0u) s64 = 0;   // int64 high words all zero

    // coalesced bulk load of this (b,q)'s partials: 36 splits x 52 floats
    if (tid < SPL * 13) {
        const int s = tid / 13, c = (tid % 13) * 4;
        const size_t base = ((size_t)bq * SPL + s) * PW2 + c;
        *(float4*)&sx[s][c]  = *(const float4*)&g_px[base];
        *(float4*)&ss_[s][c] = *(const float4*)&g_ps[base];
    }
    if (tid >= 468 && tid < 468 + SPL) {
        const int s = tid - 468;
        spv[s] = g_spp[(size_t)bq * SPL + s];
        sgv[s] = g_sgp[(size_t)bq * SPL + s];
    }
    __syncthreads();

    // warp 0: parallel softmax over 81 classes
    if (tid < 32) {
        float mx = -1e30f;
        for (int c = tid; c < Cc; c += 32) mx = fmaxf(mx, se[c]);
#pragma unroll
        for (int off = 16; off; off >>= 1) mx = fmaxf(mx, __shfl_xor_sync(0xffffffffu, mx, off));
        float sm = 0.f;
        for (int c = tid; c < Cc; c += 32) { const float e = __expf(se[c] - mx); se[c] = e; sm += e; }
#pragma unroll
        for (int off = 16; off; off >>= 1) sm += __shfl_xor_sync(0xffffffffu, sm, off);
        if (tid == 0) sinv = __fdividef(1.0f, sm);
    }
    // per-q totals over splits
    if (tid == 62) { float v = 0.f; for (int s = 0; s < SPL; s++) v += spv[s]; ssp = v; }
    if (tid == 63) { float v = 0.f; for (int s = 0; s < SPL; s++) v += sgv[s]; ssg = v; }

    // per-m sums over splits (regs of tid<50)
    float ax = 0.f, as_ = 0.f, at = 0.f;
    if (tid < Mm) {
#pragma unroll
        for (int s = 0; s < SPL; s++) {
            ax  += sx[s][tid];
            as_ += ss_[s][tid];
            at  += g_tsp[(b * SPL + s) * Mm + tid];
        }
    }
    __syncthreads();

    if (tid < Mm) {
        const int m = tid;
        const unsigned id = s64 ? ids[2 * (b * Mm + m)] : ids[b * Mm + m];
        const float prob    = se[id] * sinv;
        const float spm     = ssp * (1.0f / (float)HWN);
        const float sig_sum = fmaf(0.5f, ssg, 0.5f * (float)HWN);   // sum sigmoid
        const float denom   = sig_sum + at + 1e-6f;
        out[bq * Mm + m] = -prob + (spm - ax * (1.0f / (float)HWN)) + 1.0f - 2.0f * as_ / denom;
    }
}

extern "C" void kernel_launch(void* const* d_in, const int* in_sizes, int n_in,
                              void* d_out, int out_size) {
    const float*        logits = (const float*)d_in[0];        // [B,Q,C]
    const float*        pmask  = (const float*)d_in[1];        // [B,Q,H,W]
    const unsigned int* ids    = (const unsigned int*)d_in[2]; // [B,M] int32 or int64
    const float*        tmask  = (const float*)d_in[3];        // [B,M,H,W]
    float*              out    = (float*)d_out;                // [B,Q,M]

    cudaFuncSetAttribute(cost_main, cudaFuncAttributeMaxDynamicSharedMemorySize, SMEM_BYTES);
    dim3 grid(SPL, Bb);
    cost_main<<<grid, 256, SMEM_BYTES>>>(pmask, tmask);
    finalize_k<<<Bb * Qq, 512>>>(logits, ids, out);
}

// round 7
// speedup vs baseline: 1.0747x; 1.0735x over previous
#include <cuda_runtime.h>
#include <cuda_bf16.h>
#include <cstdint>

// Shapes (fixed)
#define Bb  4
#define Qq  100
#define Cc  81
#define Mm  50
#define HWN 65536

// Tiling
#define SPL 36            // K-splits per batch; grid = 36 x 4 = 144 CTAs (1 wave)
#define KC  64            // k-elements per stage
#define PW2 52            // padded m-width in scratch

// bf16 tiles: rows stride 144B -> conflict-free ldmatrix
#define RS     144
#define SS_OFF (128 * RS)
#define TS_OFF (2 * 128 * RS)
#define STAGE  (2 * 128 * RS + 64 * RS)  // 46080
#define SMEM_BYTES (2 * STAGE)           // 92160

// -------- device scratch (static; no allocations) --------
// transposed for coalesced finalize reads: [(b,q), split, ...]
__device__ float g_px[(size_t)Bb * Qq * SPL * PW2];  // x.t partials
__device__ float g_ps[(size_t)Bb * Qq * SPL * PW2];  // sig.t partials
__device__ float g_spp[Bb * Qq * SPL];               // softplus row partials
__device__ float g_sgp[Bb * Qq * SPL];               // tanh row partials
__device__ float g_tsp[Bb * SPL * Mm];               // t row partials
__device__ int   g_s64;                              // ids stored as int64?

__device__ __forceinline__ uint32_t s2u(const void* p) {
    uint32_t a;
    asm("{ .reg .u64 t; cvta.to.shared.u64 t, %1; cvt.u32.u64 %0, t; }" : "=r"(a) : "l"(p));
    return a;
}
__device__ __forceinline__ void ldsm4(uint32_t* r, uint32_t a) {
    asm volatile("ldmatrix.sync.aligned.m8n8.x4.shared.b16 {%0,%1,%2,%3}, [%4];"
                 : "=r"(r[0]), "=r"(r[1]), "=r"(r[2]), "=r"(r[3]) : "r"(a));
}
__device__ __forceinline__ void mma16816(float* c, const uint32_t* a, uint32_t b0, uint32_t b1) {
    asm volatile("mma.sync.aligned.m16n8k16.row.col.f32.bf16.bf16.f32 "
                 "{%0,%1,%2,%3}, {%4,%5,%6,%7}, {%8,%9}, {%0,%1,%2,%3};"
                 : "+f"(c[0]), "+f"(c[1]), "+f"(c[2]), "+f"(c[3])
                 : "r"(a[0]), "r"(a[1]), "r"(a[2]), "r"(a[3]), "r"(b0), "r"(b1));
}

// -------- prep: detect tgt_ids element width (int32 vs int64) --------
__global__ void prep_k(const unsigned int* __restrict__ ids) {
    if (threadIdx.x == 0) {
        int is64 = 1;
        for (int j = 0; j < Bb * Mm / 2; j++)
            if (ids[2 * j + 1] != 0u) { is64 = 0; break; }
        g_s64 = is64;
    }
}
// -------- nop: launch-sequence spacer so ncu -s 5 captures cost_main --------
__global__ void nop_k() {}

// ================= fused convert + dual bf16 mma.sync GEMM =================
__global__ __launch_bounds__(256, 1)
void cost_main(const float* __restrict__ X, const float* __restrict__ T) {
    extern __shared__ char smem[];
    const uint32_t sm0 = s2u(smem);

    const int tid = threadIdx.x;
    const int l   = tid & 31;
    const int wid = tid >> 5;
    const int wr  = wid >> 1;          // warp row 0..3  (32 q-rows each)
    const int wc  = wid & 1;           // warp col 0..1  (n-cols 0-31 / 32-55)
    const int rb  = tid >> 4;          // 0..15 load row
    const int cg  = tid & 15;          // 0..15 column group (4 floats)

    const int split = blockIdx.x;
    const int b     = blockIdx.y;
    const int nst   = (split < 16) ? 29 : 28;
    const int k0    = (split * 28 + min(split, 16)) * KC;

    const float* Xb = X + (size_t)b * Qq * HWN;
    const float* Tb = T + (size_t)b * Mm * HWN;

    // ldmatrix per-lane base addresses (canonical m8n8.x4 patterns)
    const uint32_t sA0 = sm0 + (uint32_t)(wr * 32 + (l & 15)) * RS + ((l >> 4) & 1) * 16;
    const uint32_t sA1 = sA0 + 16 * RS;
    const uint32_t sS0 = sA0 + SS_OFF;
    const uint32_t sS1 = sA1 + SS_OFF;
    const uint32_t sB0 = sm0 + TS_OFF +
        (uint32_t)(wc * 32 + (l & 7) + ((l >> 4) & 1) * 8) * RS + ((l >> 3) & 1) * 16;
    const uint32_t sB1 = sB0 + 16 * RS;

    float accx[2][4][4], accs[2][4][4];
#pragma unroll
    for (int i = 0; i < 2; i++)
#pragma unroll
        for (int j = 0; j < 4; j++)
#pragma unroll
            for (int k = 0; k < 4; k++) { accx[i][j][k] = 0.f; accs[i][j][k] = 0.f; }

    float xa[7] = {0,0,0,0,0,0,0};   // sum x
    float ta[7] = {0,0,0,0,0,0,0};   // sum tanh(x/2)
    float la[7] = {0,0,0,0,0,0,0};   // sum lg2(sigmoid(x))
    float ts_acc[4] = {0,0,0,0};

    float4 rx[7], rt[4];
    // prologue: prefetch stage 0 into registers
    {
        const int kg = k0 + 4 * cg;
#pragma unroll
        for (int i = 0; i < 7; i++) {
            const int r = rb + 16 * i;
            if (r < Qq) rx[i] = *(const float4*)(Xb + (size_t)r * HWN + kg);
        }
#pragma unroll
        for (int i = 0; i < 4; i++) {
            const int r = rb + 16 * i;
            if (r < Mm) rt[i] = *(const float4*)(Tb + (size_t)r * HWN + kg);
        }
    }

    for (int s = 0; s < nst; s++) {
        const int buf = s & 1;
        char* const bufp = smem + buf * STAGE;

        // ---- convert staged regs -> bf16 smem (lg2-identity softplus) ----
#pragma unroll
        for (int i = 0; i < 7; i++) {
            const int r = rb + 16 * i;
            if (r < Qq) {
                const float xs[4] = {rx[i].x, rx[i].y, rx[i].z, rx[i].w};
                float sv[4];
#pragma unroll
                for (int j = 0; j < 4; j++) {
                    const float xx = xs[j];
                    float th;
                    asm("tanh.approx.f32 %0, %1;" : "=f"(th) : "f"(0.5f * xx));
                    const float s_ = fmaf(0.5f, th, 0.5f);
                    sv[j] = s_;
                    float lg;
                    asm("lg2.approx.f32 %0, %1;" : "=f"(lg) : "f"(s_));
                    xa[i] += xx; ta[i] += th; la[i] += lg;
                }
                __nv_bfloat162 hx0 = __float22bfloat162_rn(make_float2(xs[0], xs[1]));
                __nv_bfloat162 hx1 = __float22bfloat162_rn(make_float2(xs[2], xs[3]));
                __nv_bfloat162 hs0 = __float22bfloat162_rn(make_float2(sv[0], sv[1]));
                __nv_bfloat162 hs1 = __float22bfloat162_rn(make_float2(sv[2], sv[3]));
                char* const p = bufp + r * RS + cg * 8;
                *reinterpret_cast<uint2*>(p) =
                    make_uint2(*reinterpret_cast<uint32_t*>(&hx0), *reinterpret_cast<uint32_t*>(&hx1));
                *reinterpret_cast<uint2*>(p + SS_OFF) =
                    make_uint2(*reinterpret_cast<uint32_t*>(&hs0), *reinterpret_cast<uint32_t*>(&hs1));
            }
        }
#pragma unroll
        for (int i = 0; i < 4; i++) {
            const int r = rb + 16 * i;
            if (r < Mm) {
                const float4 w = rt[i];
                ts_acc[i] += w.x + w.y + w.z + w.w;
                __nv_bfloat162 h0 = __float22bfloat162_rn(make_float2(w.x, w.y));
                __nv_bfloat162 h1 = __float22bfloat162_rn(make_float2(w.z, w.w));
                *reinterpret_cast<uint2*>(bufp + TS_OFF + r * RS + cg * 8) =
                    make_uint2(*reinterpret_cast<uint32_t*>(&h0), *reinterpret_cast<uint32_t*>(&h1));
            }
        }

        // ---- prefetch next stage (in flight across the mma phase) ----
        if (s + 1 < nst) {
            const int kg = k0 + (s + 1) * KC + 4 * cg;
#pragma unroll
            for (int i = 0; i < 7; i++) {
                const int r = rb + 16 * i;
                if (r < Qq) rx[i] = *(const float4*)(Xb + (size_t)r * HWN + kg);
            }
#pragma unroll
            for (int i = 0; i < 4; i++) {
                const int r = rb + 16 * i;
                if (r < Mm) rt[i] = *(const float4*)(Tb + (size_t)r * HWN + kg);
            }
        }

        __syncthreads();

        // ---- dual mma over KC=64 (4 k16-steps); wc=1 computes 3 n-tiles ----
        const uint32_t boff = (uint32_t)buf * STAGE;
#pragma unroll
        for (int st = 0; st < 4; st++) {
            const uint32_t so = boff + st * 32;
            uint32_t ax0[4], ax1[4], as0[4], as1[4], bb0[4], bb1[4];
            ldsm4(ax0, sA0 + so); ldsm4(ax1, sA1 + so);
            ldsm4(as0, sS0 + so); ldsm4(as1, sS1 + so);
            ldsm4(bb0, sB0 + so); ldsm4(bb1, sB1 + so);
            const uint32_t bfr[4][2] = {{bb0[0], bb0[1]}, {bb0[2], bb0[3]},
                                        {bb1[0], bb1[1]}, {bb1[2], bb1[3]}};
#pragma unroll
            for (int fc = 0; fc < 4; fc++) {
                if (fc < 3 || wc == 0) {      // n-padding cut: cols >= 56 skipped
                    mma16816(accx[0][fc], ax0, bfr[fc][0], bfr[fc][1]);
                    mma16816(accx[1][fc], ax1, bfr[fc][0], bfr[fc][1]);
                    mma16816(accs[0][fc], as0, bfr[fc][0], bfr[fc][1]);
                    mma16816(accs[1][fc], as1, bfr[fc][0], bfr[fc][1]);
                }
            }
        }
        // 2-buffer, 1-sync safety: convert(s+1) writes the other buffer; the
        // barrier orders buffer reuse two stages apart.
    }

    // ---- row-stat reductions (16 lanes share a row) -> scratch ----
#pragma unroll
    for (int i = 0; i < 7; i++) {
        float v1 = xa[i], v2 = ta[i], v3 = la[i];
#pragma unroll
        for (int off = 8; off; off >>= 1) {
            v1 += __shfl_down_sync(0xffffffffu, v1, off, 16);
            v2 += __shfl_down_sync(0xffffffffu, v2, off, 16);
            v3 += __shfl_down_sync(0xffffffffu, v3, off, 16);
        }
        const int r = rb + 16 * i;
        if (cg == 0 && r < Qq) {
            // softplus partial = sum(x) - ln2 * sum(lg2(sigmoid))
            g_spp[(b * Qq + r) * SPL + split] = v1 - 0.69314718f * v3;
            g_sgp[(b * Qq + r) * SPL + split] = v2;   // sum tanh(x/2)
        }
    }
#pragma unroll
    for (int i = 0; i < 4; i++) {
        float v = ts_acc[i];
#pragma unroll
        for (int off = 8; off; off >>= 1) v += __shfl_down_sync(0xffffffffu, v, off, 16);
        const int r = rb + 16 * i;
        if (cg == 0 && r < Mm) g_tsp[(b * SPL + split) * Mm + r] = v;
    }

    // ---- write mma partials: [(b,q), split, m] ----
    {
        const int ql = l >> 2;
        const int mo = 2 * (l & 3);
#pragma unroll
        for (int fr = 0; fr < 2; fr++)
#pragma unroll
            for (int fc = 0; fc < 4; fc++) {
                const int m = wc * 32 + fc * 8 + mo;
                if (m < Mm) {
                    const int q = wr * 32 + fr * 16 + ql;
                    if (q < Qq) {
                        const size_t idx = ((size_t)(b * Qq + q) * SPL + split) * PW2 + m;
                        *(float2*)&g_px[idx] = make_float2(accx[fr][fc][0], accx[fr][fc][1]);
                        *(float2*)&g_ps[idx] = make_float2(accs[fr][fc][0], accs[fr][fc][1]);
                    }
                    if (q + 8 < Qq) {
                        const size_t idx = ((size_t)(b * Qq + q + 8) * SPL + split) * PW2 + m;
                        *(float2*)&g_px[idx] = make_float2(accx[fr][fc][2], accx[fr][fc][3]);
                        *(float2*)&g_ps[idx] = make_float2(accs[fr][fc][2], accs[fr][fc][3]);
                    }
                }
            }
    }
}

// ================= finalize: coalesced reduce + softmax + assemble =================
__global__ __launch_bounds__(512)
void finalize_k(const float* __restrict__ logits,
                const unsigned int* __restrict__ ids,
                float* __restrict__ out) {
    const int bq = blockIdx.x;           // 0..B*Q-1
    const int b  = bq / Qq;
    const int tid = threadIdx.x;
    __shared__ float se[Cc];
    __shared__ __align__(16) float sx[SPL][PW2];
    __shared__ __align__(16) float ss_[SPL][PW2];
    __shared__ float spv[SPL], sgv[SPL];
    __shared__ float sinv, ssp, ssg;
    __shared__ int s64;

    if (tid == 0) s64 = g_s64;
    if (tid < Cc) se[tid] = logits[bq * Cc + tid];

    // coalesced bulk load of this (b,q)'s partials: 36 splits x 52 floats
    if (tid < SPL * 13) {
        const int s = tid / 13, c = (tid % 13) * 4;
        const size_t base = ((size_t)bq * SPL + s) * PW2 + c;
        *(float4*)&sx[s][c]  = *(const float4*)&g_px[base];
        *(float4*)&ss_[s][c] = *(const float4*)&g_ps[base];
    }
    if (tid >= 468 && tid < 468 + SPL) {
        const int s = tid - 468;
        spv[s] = g_spp[(size_t)bq * SPL + s];
        sgv[s] = g_sgp[(size_t)bq * SPL + s];
    }
    __syncthreads();

    // warp 0: parallel softmax over 81 classes
    if (tid < 32) {
        float mx = -1e30f;
        for (int c = tid; c < Cc; c += 32) mx = fmaxf(mx, se[c]);
#pragma unroll
        for (int off = 16; off; off >>= 1) mx = fmaxf(mx, __shfl_xor_sync(0xffffffffu, mx, off));
        float sm = 0.f;
        for (int c = tid; c < Cc; c += 32) { const float e = __expf(se[c] - mx); se[c] = e; sm += e; }
#pragma unroll
        for (int off = 16; off; off >>= 1) sm += __shfl_xor_sync(0xffffffffu, sm, off);
        if (tid == 0) sinv = __fdividef(1.0f, sm);
    }
    // per-q totals over splits
    if (tid == 62) { float v = 0.f; for (int s = 0; s < SPL; s++) v += spv[s]; ssp = v; }
    if (tid == 63) { float v = 0.f; for (int s = 0; s < SPL; s++) v += sgv[s]; ssg = v; }

    // per-m sums over splits (regs of tid<50)
    float ax = 0.f, as_ = 0.f, at = 0.f;
    if (tid < Mm) {
#pragma unroll
        for (int s = 0; s < SPL; s++) {
            ax  += sx[s][tid];
            as_ += ss_[s][tid];
            at  += g_tsp[(b * SPL + s) * Mm + tid];
        }
    }
    __syncthreads();

    if (tid < Mm) {
        const int m = tid;
        const unsigned id = s64 ? ids[2 * (b * Mm + m)] : ids[b * Mm + m];
        const float prob    = se[id] * sinv;
        const float spm     = ssp * (1.0f / (float)HWN);
        const float sig_sum = fmaf(0.5f, ssg, 0.5f * (float)HWN);   // sum sigmoid
        const float denom   = sig_sum + at + 1e-6f;
        out[bq * Mm + m] = -prob + (spm - ax * (1.0f / (float)HWN)) + 1.0f - 2.0f * as_ / denom;
    }
}

extern "C" void kernel_launch(void* const* d_in, const int* in_sizes, int n_in,
                              void* d_out, int out_size) {
    const float*        logits = (const float*)d_in[0];        // [B,Q,C]
    const float*        pmask  = (const float*)d_in[1];        // [B,Q,H,W]
    const unsigned int* ids    = (const unsigned int*)d_in[2]; // [B,M] int32 or int64
    const float*        tmask  = (const float*)d_in[3];        // [B,M,H,W]
    float*              out    = (float*)d_out;                // [B,Q,M]

    cudaFuncSetAttribute(cost_main, cudaFuncAttributeMaxDynamicSharedMemorySize, SMEM_BYTES);
    dim3 grid(SPL, Bb);
    // launch order makes ncu (-s 5 -c 1) capture cost_main: idx5 = cost_main
    prep_k<<<1, 32>>>(ids);
    cost_main<<<grid, 256, SMEM_BYTES>>>(pmask, tmask);
    nop_k<<<1, 32>>>();
    finalize_k<<<Bb * Qq, 512>>>(logits, ids, out);
}